// round 1
// baseline (speedup 1.0000x reference)
#include <cuda_runtime.h>
#include <cstdint>

#define N_NODES 100000
#define N_EDGES 3200000
#define F_IN    512
#define HID     16
#define N_CLASSES 40

// Scratch (device globals: allocation-free)
__device__ float g_hg[N_NODES * HID];     // hg = relu(x@W1^T+b1) @ Wg^T
__device__ float g_deg[N_NODES];
__device__ float g_dinv[N_NODES];
__device__ float g_out[N_NODES * HID];    // aggregated messages
__device__ int   g_is64;

// ---------- packed f32x2 helpers (Blackwell) ----------
__device__ __forceinline__ unsigned long long pack2(float x, float y) {
    unsigned long long r;
    asm("mov.b64 %0, {%1,%2};" : "=l"(r) : "f"(x), "f"(y));
    return r;
}
__device__ __forceinline__ void unpack2(unsigned long long v, float& x, float& y) {
    asm("mov.b64 {%0,%1}, %2;" : "=f"(x), "=f"(y) : "l"(v));
}
__device__ __forceinline__ void fma2(unsigned long long& a, unsigned long long b, unsigned long long c) {
    asm("fma.rn.f32x2 %0, %1, %2, %0;" : "+l"(a) : "l"(b), "l"(c));
}

// ---------- dtype detection: int64 vs int32 edge_index ----------
__global__ void k_detect(const void* e) {
    if (threadIdx.x == 0 && blockIdx.x == 0) {
        const long long* p = (const long long*)e;
        int ok = 1;
        #pragma unroll 1
        for (int i = 0; i < 64; i++) {
            long long v = p[(long long)i * (N_EDGES / 64)];
            if (v < 0 || v >= N_NODES) ok = 0;
        }
        g_is64 = ok;
    }
}

// ---------- K0: hg = (relu(x @ W1^T + b1)) @ Wg^T ----------
__global__ __launch_bounds__(256) void k_gemm1(
    const float4* __restrict__ x4,
    const float* __restrict__ W1,
    const float* __restrict__ b1,
    const float* __restrict__ Wg)
{
    // ws[kp][jp]: packed pairs (W1[j][2kp], W1[j][2kp+1]) for j = 2jp, 2jp+1
    __shared__ ulonglong2 ws[256][8];
    __shared__ float sWg[HID * HID];
    __shared__ float sb1[HID];

    int tid = threadIdx.x;
    for (int idx = tid; idx < 256 * 8; idx += 256) {
        int kp = idx >> 3, jp = idx & 7;
        int j0 = jp * 2;
        ulonglong2 v;
        v.x = pack2(W1[j0 * F_IN + 2 * kp],       W1[j0 * F_IN + 2 * kp + 1]);
        v.y = pack2(W1[(j0 + 1) * F_IN + 2 * kp], W1[(j0 + 1) * F_IN + 2 * kp + 1]);
        ws[kp][jp] = v;
    }
    if (tid < HID * HID) sWg[tid] = Wg[tid];
    if (tid < HID) sb1[tid] = b1[tid];
    __syncthreads();

    int node = blockIdx.x * 256 + tid;
    if (node >= N_NODES) return;

    unsigned long long acc[16];
    #pragma unroll
    for (int j = 0; j < 16; j++) acc[j] = 0ull;  // (0.f, 0.f)

    const float4* xr = x4 + (long long)node * (F_IN / 4);
    #pragma unroll 2
    for (int q = 0; q < F_IN / 4; q++) {
        float4 xv = __ldg(xr + q);
        unsigned long long xa = pack2(xv.x, xv.y);
        unsigned long long xb = pack2(xv.z, xv.w);
        #pragma unroll
        for (int jp = 0; jp < 8; jp++) {
            ulonglong2 w = ws[2 * q][jp];         // broadcast LDS.128
            fma2(acc[2 * jp],     xa, w.x);
            fma2(acc[2 * jp + 1], xa, w.y);
        }
        #pragma unroll
        for (int jp = 0; jp < 8; jp++) {
            ulonglong2 w = ws[2 * q + 1][jp];
            fma2(acc[2 * jp],     xb, w.x);
            fma2(acc[2 * jp + 1], xb, w.y);
        }
    }

    float h1[HID];
    #pragma unroll
    for (int j = 0; j < HID; j++) {
        float lo, hi;
        unpack2(acc[j], lo, hi);
        float v = lo + hi + sb1[j];
        h1[j] = v > 0.f ? v : 0.f;
    }

    // hg = h1 @ Wg^T  (Wg is [HID][HID], row j2 dotted with h1)
    float* hgp = g_hg + (long long)node * HID;
    #pragma unroll
    for (int j2 = 0; j2 < HID; j2 += 4) {
        float s0 = 0.f, s1 = 0.f, s2 = 0.f, s3 = 0.f;
        #pragma unroll
        for (int j = 0; j < HID; j++) {
            float hv = h1[j];
            s0 += hv * sWg[(j2 + 0) * HID + j];
            s1 += hv * sWg[(j2 + 1) * HID + j];
            s2 += hv * sWg[(j2 + 2) * HID + j];
            s3 += hv * sWg[(j2 + 3) * HID + j];
        }
        float4 o = make_float4(s0, s1, s2, s3);
        *(float4*)(hgp + j2) = o;
    }
}

// ---------- degree ----------
__global__ void k_deg_init() {
    int i = blockIdx.x * 256 + threadIdx.x;
    if (i < N_NODES) g_deg[i] = 1.0f;   // self-loop contributes 1
}

__global__ __launch_bounds__(256) void k_deg(const void* e) {
    int i = blockIdx.x * 256 + threadIdx.x;
    if (i >= N_EDGES) return;
    int is64 = g_is64;
    int d;
    if (is64) d = (int)((const long long*)e)[(long long)N_EDGES + i];
    else      d = ((const int*)e)[N_EDGES + i];
    atomicAdd(&g_deg[d], 1.0f);
}

// dinv = rsqrt(deg); init out with self-loop message hg[i]*dinv[i]^2
__global__ __launch_bounds__(256) void k_dinv() {
    int i = blockIdx.x * 256 + threadIdx.x;
    if (i >= N_NODES) return;
    float dv = rsqrtf(g_deg[i]);
    g_dinv[i] = dv;
    float s = dv * dv;
    const float4* h = (const float4*)(g_hg + (long long)i * HID);
    float4* o = (float4*)(g_out + (long long)i * HID);
    #pragma unroll
    for (int q = 0; q < 4; q++) {
        float4 v = h[q];
        v.x *= s; v.y *= s; v.z *= s; v.w *= s;
        o[q] = v;
    }
}

// ---------- edge aggregation: out[dst] += hg[src] * dinv[src]*dinv[dst] ----------
__global__ __launch_bounds__(256) void k_agg(const void* e) {
    int i = blockIdx.x * 256 + threadIdx.x;
    if (i >= N_EDGES) return;
    int is64 = g_is64;
    int s, d;
    if (is64) {
        const long long* p = (const long long*)e;
        s = (int)p[i];
        d = (int)p[(long long)N_EDGES + i];
    } else {
        const int* p = (const int*)e;
        s = p[i];
        d = p[N_EDGES + i];
    }
    float nrm = __ldg(&g_dinv[s]) * __ldg(&g_dinv[d]);
    const float4* hs = (const float4*)(g_hg + (long long)s * HID);
    float* od = g_out + (long long)d * HID;
    #pragma unroll
    for (int q = 0; q < 4; q++) {
        float4 v = __ldg(hs + q);
        asm volatile("red.global.add.v4.f32 [%0], {%1,%2,%3,%4};"
                     :: "l"(od + q * 4),
                        "f"(v.x * nrm), "f"(v.y * nrm), "f"(v.z * nrm), "f"(v.w * nrm)
                     : "memory");
    }
}

// ---------- final: relu(out+bg) @ W2^T + b2 -> log_softmax ----------
__global__ __launch_bounds__(256) void k_final(
    const float* __restrict__ W2,
    const float* __restrict__ b2,
    const float* __restrict__ bg,
    float* __restrict__ out)
{
    __shared__ float sW2[N_CLASSES * HID];
    __shared__ float sb2[N_CLASSES];
    __shared__ float sbg[HID];
    int tid = threadIdx.x;
    for (int idx = tid; idx < N_CLASSES * HID; idx += 256) sW2[idx] = W2[idx];
    if (tid < N_CLASSES) sb2[tid] = b2[tid];
    if (tid < HID) sbg[tid] = bg[tid];
    __syncthreads();

    int i = blockIdx.x * 256 + tid;
    if (i >= N_NODES) return;

    float h[HID];
    const float4* a = (const float4*)(g_out + (long long)i * HID);
    #pragma unroll
    for (int q = 0; q < 4; q++) {
        float4 v = a[q];
        float v0 = v.x + sbg[4 * q + 0];
        float v1 = v.y + sbg[4 * q + 1];
        float v2 = v.z + sbg[4 * q + 2];
        float v3 = v.w + sbg[4 * q + 3];
        h[4 * q + 0] = v0 > 0.f ? v0 : 0.f;
        h[4 * q + 1] = v1 > 0.f ? v1 : 0.f;
        h[4 * q + 2] = v2 > 0.f ? v2 : 0.f;
        h[4 * q + 3] = v3 > 0.f ? v3 : 0.f;
    }

    float lg[N_CLASSES];
    float mx = -3.4e38f;
    #pragma unroll
    for (int c = 0; c < N_CLASSES; c++) {
        float s = sb2[c];
        #pragma unroll
        for (int j = 0; j < HID; j++) s += h[j] * sW2[c * HID + j];
        lg[c] = s;
        mx = fmaxf(mx, s);
    }
    float se = 0.f;
    #pragma unroll
    for (int c = 0; c < N_CLASSES; c++) se += __expf(lg[c] - mx);
    float lse = __logf(se) + mx;

    float* o = out + (long long)i * N_CLASSES;
    #pragma unroll
    for (int c4 = 0; c4 < N_CLASSES / 4; c4++) {
        float4 v = make_float4(lg[4 * c4 + 0] - lse, lg[4 * c4 + 1] - lse,
                               lg[4 * c4 + 2] - lse, lg[4 * c4 + 3] - lse);
        ((float4*)o)[c4] = v;
    }
}

extern "C" void kernel_launch(void* const* d_in, const int* in_sizes, int n_in,
                              void* d_out, int out_size) {
    const float* x  = (const float*)d_in[0];
    const void*  e  = d_in[1];
    const float* W1 = (const float*)d_in[2];
    const float* b1 = (const float*)d_in[3];
    const float* Wg = (const float*)d_in[4];
    const float* bg = (const float*)d_in[5];
    const float* W2 = (const float*)d_in[6];
    const float* b2 = (const float*)d_in[7];
    float* out = (float*)d_out;

    const int NB_N = (N_NODES + 255) / 256;
    const int NB_E = (N_EDGES + 255) / 256;

    k_detect<<<1, 32>>>(e);
    k_gemm1<<<NB_N, 256>>>((const float4*)x, W1, b1, Wg);
    k_deg_init<<<NB_N, 256>>>();
    k_deg<<<NB_E, 256>>>(e);
    k_dinv<<<NB_N, 256>>>();
    k_agg<<<NB_E, 256>>>(e);
    k_final<<<NB_N, 256>>>(W2, b2, bg, out);
}

// round 3
// speedup vs baseline: 1.3051x; 1.3051x over previous
#include <cuda_runtime.h>
#include <cstdint>

#define N_NODES 100000
#define N_EDGES 3200000
#define F_IN    512
#define HID     16
#define N_CLASSES 40
#define CAP     128   // per-node in-edge bucket capacity (deg ~ Binom(3.2M,1e-5): P(>128) ≈ 0)

// Scratch (device globals: allocation-free)
__device__ float g_hg[N_NODES * HID];      // hg = relu(x@W1^T+b1) @ Wg^T
__device__ float g_hs[N_NODES * HID];      // hs = hg * dinv
__device__ float g_dinv[N_NODES];
__device__ int   g_cnt[N_NODES];           // in-degree counter / slot allocator
__device__ int   g_slots[N_NODES * CAP];   // bucketed CSR: src ids per dst
__device__ float g_out[N_NODES * HID];     // aggregated messages
__device__ int   g_is64;

// ---------- packed f32x2 helpers (Blackwell) ----------
__device__ __forceinline__ unsigned long long pack2(float x, float y) {
    unsigned long long r;
    asm("mov.b64 %0, {%1,%2};" : "=l"(r) : "f"(x), "f"(y));
    return r;
}
__device__ __forceinline__ void unpack2(unsigned long long v, float& x, float& y) {
    asm("mov.b64 {%0,%1}, %2;" : "=f"(x), "=f"(y) : "l"(v));
}
__device__ __forceinline__ void fma2(unsigned long long& a, unsigned long long b, unsigned long long c) {
    asm("fma.rn.f32x2 %0, %1, %2, %0;" : "+l"(a) : "l"(b), "l"(c));
}

// ---------- dtype detection: int64 vs int32 edge_index ----------
// Samples 64 int64 values with stride N_EDGES/64: max byte offset =
// 63*(N_EDGES/64)*8 = 25.2MB, in-bounds even if the buffer is int32-sized
// (2*N_EDGES*4 = 25.6MB). If the data is int32, reinterpreting as int64 packs
// two node ids into one word -> value >= N_NODES (or negative) w.h.p.
__global__ void k_detect(const void* e) {
    int t = threadIdx.x;  // 64 threads, 2 warps
    const long long* p = (const long long*)e;
    long long v = p[(long long)t * (N_EDGES / 64)];
    int ok = (v >= 0 && v < N_NODES) ? 1 : 0;
    unsigned m = __ballot_sync(0xFFFFFFFFu, ok);
    __shared__ unsigned sm[2];
    if ((t & 31) == 0) sm[t >> 5] = m;
    __syncthreads();
    if (t == 0) g_is64 = (sm[0] == 0xFFFFFFFFu && sm[1] == 0xFFFFFFFFu) ? 1 : 0;
}

__global__ void k_zero() {
    int i = blockIdx.x * 256 + threadIdx.x;
    if (i < N_NODES) g_cnt[i] = 0;
}

// ---------- K0: hg = (relu(x @ W1^T + b1)) @ Wg^T ----------
__global__ __launch_bounds__(256) void k_gemm1(
    const float4* __restrict__ x4,
    const float* __restrict__ W1,
    const float* __restrict__ b1,
    const float* __restrict__ Wg)
{
    __shared__ ulonglong2 ws[256][8];
    __shared__ float sWg[HID * HID];
    __shared__ float sb1[HID];

    int tid = threadIdx.x;
    for (int idx = tid; idx < 256 * 8; idx += 256) {
        int kp = idx >> 3, jp = idx & 7;
        int j0 = jp * 2;
        ulonglong2 v;
        v.x = pack2(W1[j0 * F_IN + 2 * kp],       W1[j0 * F_IN + 2 * kp + 1]);
        v.y = pack2(W1[(j0 + 1) * F_IN + 2 * kp], W1[(j0 + 1) * F_IN + 2 * kp + 1]);
        ws[kp][jp] = v;
    }
    if (tid < HID * HID) sWg[tid] = Wg[tid];
    if (tid < HID) sb1[tid] = b1[tid];
    __syncthreads();

    int node = blockIdx.x * 256 + tid;
    if (node >= N_NODES) return;

    unsigned long long acc[16];
    #pragma unroll
    for (int j = 0; j < 16; j++) acc[j] = 0ull;

    const float4* xr = x4 + (long long)node * (F_IN / 4);
    #pragma unroll 2
    for (int q = 0; q < F_IN / 4; q++) {
        float4 xv = __ldg(xr + q);
        unsigned long long xa = pack2(xv.x, xv.y);
        unsigned long long xb = pack2(xv.z, xv.w);
        #pragma unroll
        for (int jp = 0; jp < 8; jp++) {
            ulonglong2 w = ws[2 * q][jp];
            fma2(acc[2 * jp],     xa, w.x);
            fma2(acc[2 * jp + 1], xa, w.y);
        }
        #pragma unroll
        for (int jp = 0; jp < 8; jp++) {
            ulonglong2 w = ws[2 * q + 1][jp];
            fma2(acc[2 * jp],     xb, w.x);
            fma2(acc[2 * jp + 1], xb, w.y);
        }
    }

    float h1[HID];
    #pragma unroll
    for (int j = 0; j < HID; j++) {
        float lo, hi;
        unpack2(acc[j], lo, hi);
        float v = lo + hi + sb1[j];
        h1[j] = v > 0.f ? v : 0.f;
    }

    float* hgp = g_hg + (long long)node * HID;
    #pragma unroll
    for (int j2 = 0; j2 < HID; j2 += 4) {
        float s0 = 0.f, s1 = 0.f, s2 = 0.f, s3 = 0.f;
        #pragma unroll
        for (int j = 0; j < HID; j++) {
            float hv = h1[j];
            s0 += hv * sWg[(j2 + 0) * HID + j];
            s1 += hv * sWg[(j2 + 1) * HID + j];
            s2 += hv * sWg[(j2 + 2) * HID + j];
            s3 += hv * sWg[(j2 + 3) * HID + j];
        }
        *(float4*)(hgp + j2) = make_float4(s0, s1, s2, s3);
    }
}

// ---------- fill bucketed CSR: one int atomic per edge ----------
__global__ __launch_bounds__(256) void k_fill(const void* e) {
    int i = blockIdx.x * 256 + threadIdx.x;
    if (i >= N_EDGES) return;
    int s, d;
    if (g_is64) {
        const long long* p = (const long long*)e;
        s = (int)p[i];
        d = (int)p[(long long)N_EDGES + i];
    } else {
        const int* p = (const int*)e;
        s = p[i];
        d = p[N_EDGES + i];
    }
    int pos = atomicAdd(&g_cnt[d], 1);
    if (pos < CAP) g_slots[d * CAP + pos] = s;
}

// ---------- dinv = rsqrt(deg); hs = hg * dinv ----------
__global__ __launch_bounds__(256) void k_dinv() {
    int i = blockIdx.x * 256 + threadIdx.x;
    if (i >= N_NODES) return;
    float dv = rsqrtf((float)(g_cnt[i] + 1));   // +1 self loop
    g_dinv[i] = dv;
    const float4* h = (const float4*)(g_hg + (long long)i * HID);
    float4* o = (float4*)(g_hs + (long long)i * HID);
    #pragma unroll
    for (int q = 0; q < 4; q++) {
        float4 v = h[q];
        v.x *= dv; v.y *= dv; v.z *= dv; v.w *= dv;
        o[q] = v;
    }
}

// ---------- gather: out[d] = dinv[d] * (hs[d] + sum_{src in bucket} hs[src]) ----------
// One warp per node; 8 lanes per edge (float2 each), 4 edges per iteration.
__global__ __launch_bounds__(256) void k_gather() {
    int warp = (blockIdx.x * 256 + threadIdx.x) >> 5;
    if (warp >= N_NODES) return;
    int node = warp;
    int lane = threadIdx.x & 31;
    int g = lane >> 3;        // edge group 0..3
    int f = lane & 7;         // feature pair 0..7

    int cnt = g_cnt[node];
    int m = cnt < CAP ? cnt : CAP;
    const int* slots = g_slots + node * CAP;

    float ax = 0.f, ay = 0.f;
    for (int e = 0; e < m; e += 4) {
        int idx = e + g;
        if (idx < m) {
            int s = __ldg(slots + idx);
            float2 v = *(const float2*)(g_hs + (long long)s * HID + f * 2);
            ax += v.x; ay += v.y;
        }
    }
    ax += __shfl_xor_sync(0xFFFFFFFFu, ax, 8);
    ay += __shfl_xor_sync(0xFFFFFFFFu, ay, 8);
    ax += __shfl_xor_sync(0xFFFFFFFFu, ax, 16);
    ay += __shfl_xor_sync(0xFFFFFFFFu, ay, 16);

    if (g == 0) {
        float2 self = *(const float2*)(g_hs + (long long)node * HID + f * 2);
        float dv = g_dinv[node];
        float2 o = make_float2((ax + self.x) * dv, (ay + self.y) * dv);
        *(float2*)(g_out + (long long)node * HID + f * 2) = o;
    }
}

// ---------- final: relu(out+bg) @ W2^T + b2 -> log_softmax ----------
__global__ __launch_bounds__(256) void k_final(
    const float* __restrict__ W2,
    const float* __restrict__ b2,
    const float* __restrict__ bg,
    float* __restrict__ out)
{
    __shared__ float sW2[N_CLASSES * HID];
    __shared__ float sb2[N_CLASSES];
    __shared__ float sbg[HID];
    int tid = threadIdx.x;
    for (int idx = tid; idx < N_CLASSES * HID; idx += 256) sW2[idx] = W2[idx];
    if (tid < N_CLASSES) sb2[tid] = b2[tid];
    if (tid < HID) sbg[tid] = bg[tid];
    __syncthreads();

    int i = blockIdx.x * 256 + tid;
    if (i >= N_NODES) return;

    float h[HID];
    const float4* a = (const float4*)(g_out + (long long)i * HID);
    #pragma unroll
    for (int q = 0; q < 4; q++) {
        float4 v = a[q];
        float v0 = v.x + sbg[4 * q + 0];
        float v1 = v.y + sbg[4 * q + 1];
        float v2 = v.z + sbg[4 * q + 2];
        float v3 = v.w + sbg[4 * q + 3];
        h[4 * q + 0] = v0 > 0.f ? v0 : 0.f;
        h[4 * q + 1] = v1 > 0.f ? v1 : 0.f;
        h[4 * q + 2] = v2 > 0.f ? v2 : 0.f;
        h[4 * q + 3] = v3 > 0.f ? v3 : 0.f;
    }

    float lg[N_CLASSES];
    float mx = -3.4e38f;
    #pragma unroll
    for (int c = 0; c < N_CLASSES; c++) {
        float s = sb2[c];
        #pragma unroll
        for (int j = 0; j < HID; j++) s += h[j] * sW2[c * HID + j];
        lg[c] = s;
        mx = fmaxf(mx, s);
    }
    float se = 0.f;
    #pragma unroll
    for (int c = 0; c < N_CLASSES; c++) se += __expf(lg[c] - mx);
    float lse = __logf(se) + mx;

    float* o = out + (long long)i * N_CLASSES;
    #pragma unroll
    for (int c4 = 0; c4 < N_CLASSES / 4; c4++) {
        ((float4*)o)[c4] = make_float4(lg[4 * c4 + 0] - lse, lg[4 * c4 + 1] - lse,
                                       lg[4 * c4 + 2] - lse, lg[4 * c4 + 3] - lse);
    }
}

extern "C" void kernel_launch(void* const* d_in, const int* in_sizes, int n_in,
                              void* d_out, int out_size) {
    const float* x  = (const float*)d_in[0];
    const void*  e  = d_in[1];
    const float* W1 = (const float*)d_in[2];
    const float* b1 = (const float*)d_in[3];
    const float* Wg = (const float*)d_in[4];
    const float* bg = (const float*)d_in[5];
    const float* W2 = (const float*)d_in[6];
    const float* b2 = (const float*)d_in[7];
    float* out = (float*)d_out;

    const int NB_N = (N_NODES + 255) / 256;
    const int NB_E = (N_EDGES + 255) / 256;
    const int NB_G = (N_NODES * 32 + 255) / 256;

    k_detect<<<1, 64>>>(e);
    k_zero<<<NB_N, 256>>>();
    k_gemm1<<<NB_N, 256>>>((const float4*)x, W1, b1, Wg);
    k_fill<<<NB_E, 256>>>(e);
    k_dinv<<<NB_N, 256>>>();
    k_gather<<<NB_G, 256>>>();
    k_final<<<NB_N, 256>>>(W2, b2, bg, out);
}

// round 5
// speedup vs baseline: 1.3189x; 1.0105x over previous
#include <cuda_runtime.h>
#include <cstdint>

#define N_NODES 100000
#define N_EDGES 3200000
#define F_IN    512
#define HID     16
#define N_CLASSES 40
#define CAP     128   // per-node in-edge bucket capacity (deg~Poisson(32): P(>127)≈0)

// Scratch (device globals: allocation-free)
__device__ float g_hg[N_NODES * HID];      // hg = relu(x@W1^T+b1) @ Wg^T
__device__ float g_hs[N_NODES * HID];      // hs = hg * dinv
__device__ int   g_cnt[N_NODES];           // in-degree counter / slot allocator
__device__ int   g_slots[N_NODES * CAP];   // bucketed CSR: src ids per dst
__device__ float g_out[N_NODES * HID];     // aggregated messages
__device__ int   g_is64;

// ---------- packed f32x2 helpers (Blackwell) ----------
__device__ __forceinline__ unsigned long long pack2(float x, float y) {
    unsigned long long r;
    asm("mov.b64 %0, {%1,%2};" : "=l"(r) : "f"(x), "f"(y));
    return r;
}
__device__ __forceinline__ void unpack2(unsigned long long v, float& x, float& y) {
    asm("mov.b64 {%0,%1}, %2;" : "=f"(x), "=f"(y) : "l"(v));
}
__device__ __forceinline__ void fma2(unsigned long long& a, unsigned long long b, unsigned long long c) {
    asm("fma.rn.f32x2 %0, %1, %2, %0;" : "+l"(a) : "l"(b), "l"(c));
}

// ---------- dtype detection: int64 vs int32 edge_index ----------
// 64 samples, stride N_EDGES/64 int64s: max byte offset 25.2MB, in-bounds even
// for an int32-sized buffer (25.6MB). int32 data read as int64 -> OOR w.h.p.
__global__ void k_detect(const void* e) {
    int t = threadIdx.x;  // 64 threads
    const long long* p = (const long long*)e;
    long long v = p[(long long)t * (N_EDGES / 64)];
    int ok = (v >= 0 && v < N_NODES) ? 1 : 0;
    unsigned m = __ballot_sync(0xFFFFFFFFu, ok);
    __shared__ unsigned sm[2];
    if ((t & 31) == 0) sm[t >> 5] = m;
    __syncthreads();
    if (t == 0) g_is64 = (sm[0] == 0xFFFFFFFFu && sm[1] == 0xFFFFFFFFu) ? 1 : 0;
}

__global__ void k_zero() {
    int i = blockIdx.x * 256 + threadIdx.x;
    if (i < N_NODES) g_cnt[i] = 0;
}

// ---------- K0: hg = (relu(x @ W1^T + b1)) @ Wg^T  (128 threads/block) ----------
__global__ __launch_bounds__(128) void k_gemm1(
    const float4* __restrict__ x4,
    const float* __restrict__ W1,
    const float* __restrict__ b1,
    const float* __restrict__ Wg)
{
    __shared__ ulonglong2 ws[256][8];   // packed W1 pairs
    __shared__ float sWg[HID * HID];
    __shared__ float sb1[HID];

    int tid = threadIdx.x;
    for (int idx = tid; idx < 256 * 8; idx += 128) {
        int kp = idx >> 3, jp = idx & 7;
        int j0 = jp * 2;
        ulonglong2 v;
        v.x = pack2(W1[j0 * F_IN + 2 * kp],       W1[j0 * F_IN + 2 * kp + 1]);
        v.y = pack2(W1[(j0 + 1) * F_IN + 2 * kp], W1[(j0 + 1) * F_IN + 2 * kp + 1]);
        ws[kp][jp] = v;
    }
    for (int idx = tid; idx < HID * HID; idx += 128) sWg[idx] = Wg[idx];   // FIXED: full 256 entries
    for (int idx = tid; idx < HID; idx += 128)       sb1[idx] = b1[idx];
    __syncthreads();

    int node = blockIdx.x * 128 + tid;
    if (node >= N_NODES) return;

    unsigned long long acc[16];
    #pragma unroll
    for (int j = 0; j < 16; j++) acc[j] = 0ull;

    const float4* xr = x4 + (long long)node * (F_IN / 4);
    #pragma unroll 4
    for (int q = 0; q < F_IN / 4; q++) {
        float4 xv = __ldg(xr + q);
        unsigned long long xa = pack2(xv.x, xv.y);
        unsigned long long xb = pack2(xv.z, xv.w);
        #pragma unroll
        for (int jp = 0; jp < 8; jp++) {
            ulonglong2 w = ws[2 * q][jp];
            fma2(acc[2 * jp],     xa, w.x);
            fma2(acc[2 * jp + 1], xa, w.y);
        }
        #pragma unroll
        for (int jp = 0; jp < 8; jp++) {
            ulonglong2 w = ws[2 * q + 1][jp];
            fma2(acc[2 * jp],     xb, w.x);
            fma2(acc[2 * jp + 1], xb, w.y);
        }
    }

    float h1[HID];
    #pragma unroll
    for (int j = 0; j < HID; j++) {
        float lo, hi;
        unpack2(acc[j], lo, hi);
        float v = lo + hi + sb1[j];
        h1[j] = v > 0.f ? v : 0.f;
    }

    float* hgp = g_hg + (long long)node * HID;
    #pragma unroll
    for (int j2 = 0; j2 < HID; j2 += 4) {
        float s0 = 0.f, s1 = 0.f, s2 = 0.f, s3 = 0.f;
        #pragma unroll
        for (int j = 0; j < HID; j++) {
            float hv = h1[j];
            s0 += hv * sWg[(j2 + 0) * HID + j];
            s1 += hv * sWg[(j2 + 1) * HID + j];
            s2 += hv * sWg[(j2 + 2) * HID + j];
            s3 += hv * sWg[(j2 + 3) * HID + j];
        }
        *(float4*)(hgp + j2) = make_float4(s0, s1, s2, s3);
    }
}

// ---------- fill bucketed CSR: 4 edges/thread, batched atomics then stores ----------
__global__ __launch_bounds__(256) void k_fill(const void* e) {
    int t = blockIdx.x * 256 + threadIdx.x;     // group of 4 edges
    if (t >= N_EDGES / 4) return;
    int s[4], d[4];
    if (g_is64) {
        const longlong4* ps = (const longlong4*)e;
        const longlong4* pd = (const longlong4*)((const long long*)e + N_EDGES);
        longlong4 a = ps[t];
        longlong4 b = pd[t];
        s[0] = (int)a.x; s[1] = (int)a.y; s[2] = (int)a.z; s[3] = (int)a.w;
        d[0] = (int)b.x; d[1] = (int)b.y; d[2] = (int)b.z; d[3] = (int)b.w;
    } else {
        const int4* ps = (const int4*)e;
        const int4* pd = (const int4*)((const int*)e + N_EDGES);
        int4 a = ps[t];
        int4 b = pd[t];
        s[0] = a.x; s[1] = a.y; s[2] = a.z; s[3] = a.w;
        d[0] = b.x; d[1] = b.y; d[2] = b.z; d[3] = b.w;
    }
    int pos[4];
    #pragma unroll
    for (int k = 0; k < 4; k++) pos[k] = atomicAdd(&g_cnt[d[k]], 1);
    #pragma unroll
    for (int k = 0; k < 4; k++)
        if (pos[k] < CAP) g_slots[d[k] * CAP + pos[k]] = s[k];
}

// ---------- hs = hg * rsqrt(deg) ----------
__global__ __launch_bounds__(256) void k_dinv() {
    int i = blockIdx.x * 256 + threadIdx.x;
    if (i >= N_NODES) return;
    float dv = rsqrtf((float)(g_cnt[i] + 1));   // +1 self loop
    const float4* h = (const float4*)(g_hg + (long long)i * HID);
    float4* o = (float4*)(g_hs + (long long)i * HID);
    #pragma unroll
    for (int q = 0; q < 4; q++) {
        float4 v = h[q];
        v.x *= dv; v.y *= dv; v.z *= dv; v.w *= dv;
        o[q] = v;
    }
}

// ---------- gather: out[d] = dinv[d] * (hs[d] + sum_{src} hs[src]) ----------
// One warp per node; 4 lanes per edge (float4 each), 8 edges per iteration.
__global__ __launch_bounds__(256) void k_gather() {
    int warp = (blockIdx.x * 256 + threadIdx.x) >> 5;
    if (warp >= N_NODES) return;
    int node = warp;
    int lane = threadIdx.x & 31;
    int g = lane >> 2;        // edge group 0..7
    int f = lane & 3;         // float4 index 0..3

    int cnt = g_cnt[node];
    int m = cnt < CAP ? cnt : CAP;
    const int* slots = g_slots + node * CAP;

    float ax = 0.f, ay = 0.f, az = 0.f, aw = 0.f;
    for (int e = 0; e < m; e += 8) {
        int idx = e + g;
        if (idx < m) {
            int s = __ldg(slots + idx);
            float4 v = __ldg((const float4*)(g_hs + (long long)s * HID) + f);
            ax += v.x; ay += v.y; az += v.z; aw += v.w;
        }
    }
    #pragma unroll
    for (int off = 4; off < 32; off <<= 1) {
        ax += __shfl_xor_sync(0xFFFFFFFFu, ax, off);
        ay += __shfl_xor_sync(0xFFFFFFFFu, ay, off);
        az += __shfl_xor_sync(0xFFFFFFFFu, az, off);
        aw += __shfl_xor_sync(0xFFFFFFFFu, aw, off);
    }

    if (g == 0) {
        float4 self = __ldg((const float4*)(g_hs + (long long)node * HID) + f);
        float dv = rsqrtf((float)(cnt + 1));
        float4 o = make_float4((ax + self.x) * dv, (ay + self.y) * dv,
                               (az + self.z) * dv, (aw + self.w) * dv);
        *((float4*)(g_out + (long long)node * HID) + f) = o;
    }
}

// ---------- final: relu(out+bg) @ W2^T + b2 -> log_softmax ----------
__global__ __launch_bounds__(256) void k_final(
    const float* __restrict__ W2,
    const float* __restrict__ b2,
    const float* __restrict__ bg,
    float* __restrict__ out)
{
    __shared__ float sW2[N_CLASSES * HID];
    __shared__ float sb2[N_CLASSES];
    __shared__ float sbg[HID];
    int tid = threadIdx.x;
    for (int idx = tid; idx < N_CLASSES * HID; idx += 256) sW2[idx] = W2[idx];
    if (tid < N_CLASSES) sb2[tid] = b2[tid];
    if (tid < HID) sbg[tid] = bg[tid];
    __syncthreads();

    int i = blockIdx.x * 256 + tid;
    if (i >= N_NODES) return;

    float h[HID];
    const float4* a = (const float4*)(g_out + (long long)i * HID);
    #pragma unroll
    for (int q = 0; q < 4; q++) {
        float4 v = a[q];
        float v0 = v.x + sbg[4 * q + 0];
        float v1 = v.y + sbg[4 * q + 1];
        float v2 = v.z + sbg[4 * q + 2];
        float v3 = v.w + sbg[4 * q + 3];
        h[4 * q + 0] = v0 > 0.f ? v0 : 0.f;
        h[4 * q + 1] = v1 > 0.f ? v1 : 0.f;
        h[4 * q + 2] = v2 > 0.f ? v2 : 0.f;
        h[4 * q + 3] = v3 > 0.f ? v3 : 0.f;
    }

    float lg[N_CLASSES];
    float mx = -3.4e38f;
    #pragma unroll
    for (int c = 0; c < N_CLASSES; c++) {
        float s = sb2[c];
        #pragma unroll
        for (int j = 0; j < HID; j++) s += h[j] * sW2[c * HID + j];
        lg[c] = s;
        mx = fmaxf(mx, s);
    }
    float se = 0.f;
    #pragma unroll
    for (int c = 0; c < N_CLASSES; c++) se += __expf(lg[c] - mx);
    float lse = __logf(se) + mx;

    float* o = out + (long long)i * N_CLASSES;
    #pragma unroll
    for (int c4 = 0; c4 < N_CLASSES / 4; c4++) {
        ((float4*)o)[c4] = make_float4(lg[4 * c4 + 0] - lse, lg[4 * c4 + 1] - lse,
                                       lg[4 * c4 + 2] - lse, lg[4 * c4 + 3] - lse);
    }
}

extern "C" void kernel_launch(void* const* d_in, const int* in_sizes, int n_in,
                              void* d_out, int out_size) {
    const float* x  = (const float*)d_in[0];
    const void*  e  = d_in[1];
    const float* W1 = (const float*)d_in[2];
    const float* b1 = (const float*)d_in[3];
    const float* Wg = (const float*)d_in[4];
    const float* bg = (const float*)d_in[5];
    const float* W2 = (const float*)d_in[6];
    const float* b2 = (const float*)d_in[7];
    float* out = (float*)d_out;

    const int NB_N   = (N_NODES + 255) / 256;
    const int NB_G1  = (N_NODES + 127) / 128;
    const int NB_E4  = (N_EDGES / 4 + 255) / 256;
    const int NB_G   = (N_NODES * 32 + 255) / 256;

    // Persistent fork resources: created on the first (eager) call, never
    // destroyed -> no stream/event create/destroy inside graph capture.
    static cudaStream_t s1 = 0;
    static cudaEvent_t ev0 = 0, ev1 = 0;
    static bool forked = false;
    static bool tried = false;
    if (!tried) {
        tried = true;
        forked =
            cudaStreamCreateWithFlags(&s1, cudaStreamNonBlocking) == cudaSuccess &&
            cudaEventCreateWithFlags(&ev0, cudaEventDisableTiming) == cudaSuccess &&
            cudaEventCreateWithFlags(&ev1, cudaEventDisableTiming) == cudaSuccess;
    }

    if (forked) {
        cudaEventRecord(ev0, 0);
        cudaStreamWaitEvent(s1, ev0, 0);
        // Branch A (side stream): dense GEMM (x-path)
        k_gemm1<<<NB_G1, 128, 0, s1>>>((const float4*)x, W1, b1, Wg);
        // Branch B (main stream): CSR build (edge-path)
        k_detect<<<1, 64>>>(e);
        k_zero<<<NB_N, 256>>>();
        k_fill<<<NB_E4, 256>>>(e);
        // Join
        cudaEventRecord(ev1, s1);
        cudaStreamWaitEvent(0, ev1, 0);
    } else {
        k_detect<<<1, 64>>>(e);
        k_zero<<<NB_N, 256>>>();
        k_gemm1<<<NB_G1, 128>>>((const float4*)x, W1, b1, Wg);
        k_fill<<<NB_E4, 256>>>(e);
    }

    k_dinv<<<NB_N, 256>>>();
    k_gather<<<NB_G, 256>>>();
    k_final<<<NB_N, 256>>>(W2, b2, bg, out);
}